// round 14
// baseline (speedup 1.0000x reference)
#include <cuda_runtime.h>
#include <cuda.h>
#include <cuda_fp16.h>
#include <cstdint>

// ---------------- problem constants ----------------
static constexpr int M_TOTAL = 8192;   // B*S = 4*2048
static constexpr int N_TOTAL = 4096;   // out channels
static constexpr int K_TOTAL = 4096;   // in channels

static constexpr int TM = 128;         // CTA tile M
static constexpr int TN = 256;         // CTA tile N
static constexpr int TK = 64;          // K per stage (64 fp16 = 128B row -> SW128)
static constexpr int KITERS = K_TOTAL / TK;     // 64
static constexpr int STAGES = 4;
static constexpr int A_STAGE_BYTES = TM * TK * 2;   // 16384
static constexpr int B_STAGE_BYTES = TN * TK * 2;   // 32768
static constexpr int STAGE_BYTES = A_STAGE_BYTES + B_STAGE_BYTES;   // 49152
static constexpr unsigned SMEM_BYTES = 1024 + STAGES * STAGE_BYTES + 1024;

static constexpr int NCONS = 16;       // consumer warps (4M x 4N)
static constexpr int NTHREADS = (NCONS + 1) * 32;   // 544

// fused prep split: blocks [0, W_BLOCKS) dequant W, [W_BLOCKS, +X_BLOCKS) cvt x
static constexpr int W_BLOCKS = (N_TOTAL * K_TOTAL / 16) / 256;   // 4096
static constexpr int X_BLOCKS = (M_TOTAL * K_TOTAL / 16) / 256;   // 8192

// ---------------- device scratch (static: allocation-free) ----------------
__device__ __half g_wq[(size_t)N_TOTAL * K_TOTAL];  // dequantized weight fp16 [N,K]
__device__ __half g_xh[(size_t)M_TOTAL * K_TOTAL];  // x fp16 [M,K]

// ---------------- PTX helpers (sm_90-base features only) ----------------
__device__ __forceinline__ uint32_t smem_u32(const void* p) {
    return (uint32_t)__cvta_generic_to_shared(p);
}

__device__ __forceinline__ bool elect_one() {
    uint32_t pred;
    asm volatile(
        "{\n\t.reg .pred p;\n\t"
        "elect.sync _|p, 0xFFFFFFFF;\n\t"
        "selp.b32 %0, 1, 0, p;\n\t}"
        : "=r"(pred));
    return pred != 0;
}

#define MBARRIER_INIT(addr, cnt) \
    asm volatile("mbarrier.init.shared.b64 [%0], %1;" :: "r"(addr), "r"(cnt) : "memory")

#define MBARRIER_EXPECT_TX(addr, bytes) \
    asm volatile("mbarrier.arrive.expect_tx.shared.b64 _, [%0], %1;" :: "r"(addr), "r"(bytes) : "memory")

#define MBARRIER_ARRIVE(addr) \
    asm volatile("mbarrier.arrive.shared.b64 _, [%0];" :: "r"(addr) : "memory")

__device__ __forceinline__ void mbar_wait(uint32_t mbar, uint32_t parity) {
    asm volatile(
        "{\n\t.reg .pred P;\n\t"
        "WAIT_%=:\n\t"
        "mbarrier.try_wait.parity.acquire.cta.shared::cta.b64 P, [%0], %1, 0x989680;\n\t"
        "@P bra.uni DONE_%=;\n\t"
        "bra.uni WAIT_%=;\n\t"
        "DONE_%=:\n\t}"
        :: "r"(mbar), "r"(parity) : "memory");
}

__device__ __forceinline__ void tma_load_2d(uint32_t dst, const void* map,
                                            int32_t cx, int32_t cy, uint32_t mbar) {
    asm volatile(
        "cp.async.bulk.tensor.2d.shared::cta.global.tile.mbarrier::complete_tx::bytes "
        "[%0], [%1, {%2, %3}], [%4];"
        :: "r"(dst), "l"(map), "r"(cx), "r"(cy), "r"(mbar) : "memory");
}

#define LDSM_X4(r, addr) \
    asm volatile("ldmatrix.sync.aligned.m8n8.x4.shared.b16 {%0,%1,%2,%3}, [%4];" \
        : "=r"((r)[0]), "=r"((r)[1]), "=r"((r)[2]), "=r"((r)[3]) : "r"(addr))

__device__ __forceinline__ void mma16816(float* d, const uint32_t* a,
                                         uint32_t b0, uint32_t b1) {
    asm volatile(
        "mma.sync.aligned.m16n8k16.row.col.f32.f16.f16.f32 "
        "{%0,%1,%2,%3}, {%4,%5,%6,%7}, {%8,%9}, {%0,%1,%2,%3};"
        : "+f"(d[0]), "+f"(d[1]), "+f"(d[2]), "+f"(d[3])
        : "r"(a[0]), "r"(a[1]), "r"(a[2]), "r"(a[3]), "r"(b0), "r"(b1));
}

// ---------------- kernel 1: fused prep (dequant W + convert x), MLP=4 -------
// Per-thread bodies identical to the proven split kernels (16 elems/thread);
// merged into one grid so cvt blocks backfill SMs as dequant blocks drain.
// Dequant is bit-exact vs reference: po2 scale (w*(1/s)==w/s exactly),
// rintf = half-even round, (q-zp)*s = small-int * po2 -> exact in fp16.
__global__ void __launch_bounds__(256) prep_kernel(
    const float4* __restrict__ w4,
    const float* __restrict__ sc,
    const float* __restrict__ zp,
    uint4* __restrict__ wq,
    const float4* __restrict__ x4,
    uint4* __restrict__ xh)
{
    const int b = blockIdx.x;
    if (b < W_BLOCKS) {
        int i = b * 256 + threadIdx.x;      // 16 elems per thread
        int e0 = i << 4;
        int o = e0 >> 12;
        int gidx = (o << 7) + ((e0 >> 5) & 127);
        float4 v[4];
        #pragma unroll
        for (int j = 0; j < 4; j++) v[j] = w4[i * 4 + j];
        float s = sc[gidx];
        float z = zp[gidx];
        float inv = 1.0f / s;
        uint32_t h[8];
        #pragma unroll
        for (int j = 0; j < 4; j++) {
            float q0 = fminf(15.0f, fmaxf(0.0f, rintf(__fmaf_rn(v[j].x, inv, z))));
            float q1 = fminf(15.0f, fmaxf(0.0f, rintf(__fmaf_rn(v[j].y, inv, z))));
            float q2 = fminf(15.0f, fmaxf(0.0f, rintf(__fmaf_rn(v[j].z, inv, z))));
            float q3 = fminf(15.0f, fmaxf(0.0f, rintf(__fmaf_rn(v[j].w, inv, z))));
            __half2 h0 = __floats2half2_rn((q0 - z) * s, (q1 - z) * s);
            __half2 h1 = __floats2half2_rn((q2 - z) * s, (q3 - z) * s);
            h[j * 2]     = *reinterpret_cast<uint32_t*>(&h0);
            h[j * 2 + 1] = *reinterpret_cast<uint32_t*>(&h1);
        }
        wq[i * 2]     = make_uint4(h[0], h[1], h[2], h[3]);
        wq[i * 2 + 1] = make_uint4(h[4], h[5], h[6], h[7]);
    } else {
        int i = (b - W_BLOCKS) * 256 + threadIdx.x;   // 16 elems per thread
        float4 v[4];
        #pragma unroll
        for (int j = 0; j < 4; j++) v[j] = x4[i * 4 + j];
        uint32_t h[8];
        #pragma unroll
        for (int j = 0; j < 4; j++) {
            __half2 h0 = __floats2half2_rn(v[j].x, v[j].y);
            __half2 h1 = __floats2half2_rn(v[j].z, v[j].w);
            h[j * 2]     = *reinterpret_cast<uint32_t*>(&h0);
            h[j * 2 + 1] = *reinterpret_cast<uint32_t*>(&h1);
        }
        xh[i * 2]     = make_uint4(h[0], h[1], h[2], h[3]);
        xh[i * 2 + 1] = make_uint4(h[4], h[5], h[6], h[7]);
    }
}

// ---------------- kernel 2: HMMA GEMM + bias (best-measured structure) ------
// CTA 128x256, K staged by 64 with a 4-deep TMA pipeline.
// 16 consumer warps (4Mx4N grid, 32x64 warp tiles, mma.m16n8k16, f32 accum),
// 1 producer warp (warp 16) issuing TMA from a single elected thread.
__global__ void __launch_bounds__(NTHREADS, 1) qgemm_kernel(
    const __grid_constant__ CUtensorMap tmA,
    const __grid_constant__ CUtensorMap tmB,
    const float* __restrict__ bias,
    float* __restrict__ out)
{
    extern __shared__ char smem_raw[];
    uint32_t sb_raw = smem_u32(smem_raw);
    uint32_t sb = (sb_raw + 1023u) & ~1023u;   // 1024-align for SW128 atoms

    const int tid = threadIdx.x;
    const int wid = tid >> 5;
    const int lane = tid & 31;
    const int n0 = blockIdx.x * TN;     // x over N (16) so a wave shares A tiles
    const int m0 = blockIdx.y * TM;     // y over M (64)

    const uint32_t mb_full0  = sb;        // 4 x 8B
    const uint32_t mb_empty0 = sb + 64;   // 4 x 8B
    const uint32_t stage0 = sb + 1024;

    if (tid == 0) {
        #pragma unroll
        for (int s = 0; s < STAGES; s++) {
            MBARRIER_INIT(mb_full0 + 8 * s, 1);       // expect_tx arrival
            MBARRIER_INIT(mb_empty0 + 8 * s, NCONS);  // consumer warps
        }
    }
    __syncthreads();

    if (wid == NCONS) {
        // -------- producer --------
        if (elect_one()) {
            for (int kt = 0; kt < KITERS; kt++) {
                int s = kt & (STAGES - 1);
                uint32_t parity = 1u ^ ((kt >> 2) & 1u);
                mbar_wait(mb_empty0 + 8 * s, parity);
                uint32_t aDst = stage0 + s * STAGE_BYTES;
                MBARRIER_EXPECT_TX(mb_full0 + 8 * s, (uint32_t)STAGE_BYTES);
                tma_load_2d(aDst, &tmA, kt * TK, m0, mb_full0 + 8 * s);
                tma_load_2d(aDst + A_STAGE_BYTES, &tmB, kt * TK, n0, mb_full0 + 8 * s);
            }
        }
        return;
    }

    // -------- consumers: 4 warps over M (32 rows each), 4 over N (64 cols) ----
    const int wm = wid & 3;
    const int wn = wid >> 2;
    const int laneRow = lane & 15;
    const int laneKh = lane >> 4;
    const uint32_t swmask = (uint32_t)((lane & 7) << 4);
    const int g = lane >> 2;       // quad row
    const int t4 = lane & 3;       // quad col

    float acc[2][8][4];
    #pragma unroll
    for (int i = 0; i < 2; i++)
        #pragma unroll
        for (int j = 0; j < 8; j++)
            #pragma unroll
            for (int c = 0; c < 4; c++) acc[i][j][c] = 0.0f;

    // per-lane invariant parts of ldmatrix addresses
    const uint32_t aLane = (uint32_t)(laneRow * 128);
    const uint32_t kLanePart = (uint32_t)(laneKh * 16);

    #pragma unroll 1
    for (int kt = 0; kt < KITERS; kt++) {
        int s = kt & (STAGES - 1);
        uint32_t parity = (kt >> 2) & 1u;
        mbar_wait(mb_full0 + 8 * s, parity);

        uint32_t aBase = stage0 + s * STAGE_BYTES;
        uint32_t bBase = aBase + A_STAGE_BYTES;
        uint32_t aWarp = aBase + (uint32_t)(wm * 32) * 128 + aLane;
        uint32_t bWarp = bBase + (uint32_t)(wn * 64) * 128 + aLane;

        #pragma unroll
        for (int kq = 0; kq < 4; kq++) {
            uint32_t kcol = (((uint32_t)(kq * 32) + kLanePart) ^ swmask);
            uint32_t af[2][4];
            #pragma unroll
            for (int mi = 0; mi < 2; mi++)
                LDSM_X4(af[mi], aWarp + (uint32_t)(mi * 16 * 128) + kcol);
            uint32_t bf[4][4];
            #pragma unroll
            for (int nq = 0; nq < 4; nq++)
                LDSM_X4(bf[nq], bWarp + (uint32_t)(nq * 16 * 128) + kcol);
            #pragma unroll
            for (int mi = 0; mi < 2; mi++) {
                #pragma unroll
                for (int nq = 0; nq < 4; nq++) {
                    mma16816(acc[mi][2 * nq],     af[mi], bf[nq][0], bf[nq][2]);
                    mma16816(acc[mi][2 * nq + 1], af[mi], bf[nq][1], bf[nq][3]);
                }
            }
        }
        __syncwarp();
        if (lane == 0) MBARRIER_ARRIVE(mb_empty0 + 8 * s);
    }

    // -------- epilogue: bias + store --------
    const float2* b2 = reinterpret_cast<const float2*>(bias);
    #pragma unroll
    for (int mi = 0; mi < 2; mi++) {
        int mrow = m0 + wm * 32 + mi * 16 + g;
        #pragma unroll
        for (int nj = 0; nj < 8; nj++) {
            int col = n0 + wn * 64 + nj * 8 + 2 * t4;
            float2 bv = __ldg(&b2[col >> 1]);
            float2 v0, v1;
            v0.x = acc[mi][nj][0] + bv.x;
            v0.y = acc[mi][nj][1] + bv.y;
            v1.x = acc[mi][nj][2] + bv.x;
            v1.y = acc[mi][nj][3] + bv.y;
            *reinterpret_cast<float2*>(out + (size_t)mrow * N_TOTAL + col) = v0;
            *reinterpret_cast<float2*>(out + (size_t)(mrow + 8) * N_TOTAL + col) = v1;
        }
    }
}

// ---------------- host launch ----------------
typedef CUresult (*EncodeFn)(CUtensorMap*, CUtensorMapDataType, cuuint32_t, void*,
                             const cuuint64_t*, const cuuint64_t*, const cuuint32_t*,
                             const cuuint32_t*, CUtensorMapInterleave, CUtensorMapSwizzle,
                             CUtensorMapL2promotion, CUtensorMapFloatOOBfill);

extern "C" void kernel_launch(void* const* d_in, const int* in_sizes, int n_in,
                              void* d_out, int out_size) {
    const float* x    = (const float*)d_in[0];
    const float* w    = (const float*)d_in[1];
    const float* bias = (const float*)d_in[2];
    const float* sc   = (const float*)d_in[3];
    const float* zp   = (const float*)d_in[4];
    float* out = (float*)d_out;

    void* wq_ptr = nullptr;
    void* xh_ptr = nullptr;
    cudaGetSymbolAddress(&wq_ptr, g_wq);
    cudaGetSymbolAddress(&xh_ptr, g_xh);

    prep_kernel<<<W_BLOCKS + X_BLOCKS, 256>>>(
        (const float4*)w, sc, zp, (uint4*)wq_ptr,
        (const float4*)x, (uint4*)xh_ptr);

    void* fnp = nullptr;
    cudaDriverEntryPointQueryResult qres;
    cudaGetDriverEntryPointByVersion("cuTensorMapEncodeTiled", &fnp, 12000,
                                     cudaEnableDefault, &qres);
    if (!fnp) return;
    EncodeFn enc = (EncodeFn)fnp;

    CUtensorMap tmA, tmB;
    {
        cuuint64_t dims[2] = {(cuuint64_t)K_TOTAL, (cuuint64_t)M_TOTAL};
        cuuint64_t str[1]  = {(cuuint64_t)K_TOTAL * 2};
        cuuint32_t box[2]  = {(cuuint32_t)TK, (cuuint32_t)TM};
        cuuint32_t es[2]   = {1, 1};
        enc(&tmA, CU_TENSOR_MAP_DATA_TYPE_FLOAT16, 2, xh_ptr, dims, str, box, es,
            CU_TENSOR_MAP_INTERLEAVE_NONE, CU_TENSOR_MAP_SWIZZLE_128B,
            CU_TENSOR_MAP_L2_PROMOTION_L2_128B, CU_TENSOR_MAP_FLOAT_OOB_FILL_NONE);
    }
    {
        cuuint64_t dims[2] = {(cuuint64_t)K_TOTAL, (cuuint64_t)N_TOTAL};
        cuuint64_t str[1]  = {(cuuint64_t)K_TOTAL * 2};
        cuuint32_t box[2]  = {(cuuint32_t)TK, (cuuint32_t)TN};
        cuuint32_t es[2]   = {1, 1};
        enc(&tmB, CU_TENSOR_MAP_DATA_TYPE_FLOAT16, 2, wq_ptr, dims, str, box, es,
            CU_TENSOR_MAP_INTERLEAVE_NONE, CU_TENSOR_MAP_SWIZZLE_128B,
            CU_TENSOR_MAP_L2_PROMOTION_L2_128B, CU_TENSOR_MAP_FLOAT_OOB_FILL_NONE);
    }

    cudaFuncSetAttribute(qgemm_kernel, cudaFuncAttributeMaxDynamicSharedMemorySize,
                         (int)SMEM_BYTES);
    qgemm_kernel<<<dim3(N_TOTAL / TN, M_TOTAL / TM, 1), NTHREADS, SMEM_BYTES>>>(
        tmA, tmB, bias, out);
}

// round 15
// speedup vs baseline: 1.0026x; 1.0026x over previous
#include <cuda_runtime.h>
#include <cuda.h>
#include <cuda_fp16.h>
#include <cstdint>

// ---------------- problem constants ----------------
static constexpr int M_TOTAL = 8192;   // B*S = 4*2048
static constexpr int N_TOTAL = 4096;   // out channels
static constexpr int K_TOTAL = 4096;   // in channels

static constexpr int TM = 128;         // CTA tile M
static constexpr int TN = 256;         // CTA tile N
static constexpr int TK = 64;          // K per stage (64 fp16 = 128B row -> SW128)
static constexpr int KITERS = K_TOTAL / TK;     // 64
static constexpr int STAGES = 4;
static constexpr int A_STAGE_BYTES = TM * TK * 2;   // 16384
static constexpr int B_STAGE_BYTES = TN * TK * 2;   // 32768
static constexpr int STAGE_BYTES = A_STAGE_BYTES + B_STAGE_BYTES;   // 49152
static constexpr unsigned SMEM_BYTES = 1024 + STAGES * STAGE_BYTES + 1024;

static constexpr int NCONS = 16;       // consumer warps (4M x 4N)
static constexpr int NTHREADS = (NCONS + 1) * 32;   // 544

// fused prep split: blocks [0, W_BLOCKS) dequant W, [W_BLOCKS, +X_BLOCKS) cvt x
static constexpr int W_BLOCKS = (N_TOTAL * K_TOTAL / 16) / 256;   // 4096
static constexpr int X_BLOCKS = (M_TOTAL * K_TOTAL / 16) / 256;   // 8192

// ---------------- device scratch (static: allocation-free) ----------------
__device__ __half g_wq[(size_t)N_TOTAL * K_TOTAL];  // dequantized weight fp16 [N,K]
__device__ __half g_xh[(size_t)M_TOTAL * K_TOTAL];  // x fp16 [M,K]

// ---------------- PTX helpers (sm_90-base features only) ----------------
__device__ __forceinline__ uint32_t smem_u32(const void* p) {
    return (uint32_t)__cvta_generic_to_shared(p);
}

__device__ __forceinline__ bool elect_one() {
    uint32_t pred;
    asm volatile(
        "{\n\t.reg .pred p;\n\t"
        "elect.sync _|p, 0xFFFFFFFF;\n\t"
        "selp.b32 %0, 1, 0, p;\n\t}"
        : "=r"(pred));
    return pred != 0;
}

#define MBARRIER_INIT(addr, cnt) \
    asm volatile("mbarrier.init.shared.b64 [%0], %1;" :: "r"(addr), "r"(cnt) : "memory")

#define MBARRIER_EXPECT_TX(addr, bytes) \
    asm volatile("mbarrier.arrive.expect_tx.shared.b64 _, [%0], %1;" :: "r"(addr), "r"(bytes) : "memory")

#define MBARRIER_ARRIVE(addr) \
    asm volatile("mbarrier.arrive.shared.b64 _, [%0];" :: "r"(addr) : "memory")

__device__ __forceinline__ void mbar_wait(uint32_t mbar, uint32_t parity) {
    asm volatile(
        "{\n\t.reg .pred P;\n\t"
        "WAIT_%=:\n\t"
        "mbarrier.try_wait.parity.acquire.cta.shared::cta.b64 P, [%0], %1, 0x989680;\n\t"
        "@P bra.uni DONE_%=;\n\t"
        "bra.uni WAIT_%=;\n\t"
        "DONE_%=:\n\t}"
        :: "r"(mbar), "r"(parity) : "memory");
}

__device__ __forceinline__ void tma_load_2d(uint32_t dst, const void* map,
                                            int32_t cx, int32_t cy, uint32_t mbar) {
    asm volatile(
        "cp.async.bulk.tensor.2d.shared::cta.global.tile.mbarrier::complete_tx::bytes "
        "[%0], [%1, {%2, %3}], [%4];"
        :: "r"(dst), "l"(map), "r"(cx), "r"(cy), "r"(mbar) : "memory");
}

#define LDSM_X4(r, addr) \
    asm volatile("ldmatrix.sync.aligned.m8n8.x4.shared.b16 {%0,%1,%2,%3}, [%4];" \
        : "=r"((r)[0]), "=r"((r)[1]), "=r"((r)[2]), "=r"((r)[3]) : "r"(addr))

__device__ __forceinline__ void mma16816(float* d, const uint32_t* a,
                                         uint32_t b0, uint32_t b1) {
    asm volatile(
        "mma.sync.aligned.m16n8k16.row.col.f32.f16.f16.f32 "
        "{%0,%1,%2,%3}, {%4,%5,%6,%7}, {%8,%9}, {%0,%1,%2,%3};"
        : "+f"(d[0]), "+f"(d[1]), "+f"(d[2]), "+f"(d[3])
        : "r"(a[0]), "r"(a[1]), "r"(a[2]), "r"(a[3]), "r"(b0), "r"(b1));
}

// ---------------- kernel 1: fused prep (dequant W + convert x), MLP=4 -------
// Per-thread bodies identical to the proven split kernels (16 elems/thread);
// merged into one grid so cvt blocks backfill SMs as dequant blocks drain.
// Dequant is bit-exact vs reference: po2 scale (w*(1/s)==w/s exactly),
// rintf = half-even round, (q-zp)*s = small-int * po2 -> exact in fp16.
__global__ void __launch_bounds__(256) prep_kernel(
    const float4* __restrict__ w4,
    const float* __restrict__ sc,
    const float* __restrict__ zp,
    uint4* __restrict__ wq,
    const float4* __restrict__ x4,
    uint4* __restrict__ xh)
{
    const int b = blockIdx.x;
    if (b < W_BLOCKS) {
        int i = b * 256 + threadIdx.x;      // 16 elems per thread
        int e0 = i << 4;
        int o = e0 >> 12;
        int gidx = (o << 7) + ((e0 >> 5) & 127);
        float4 v[4];
        #pragma unroll
        for (int j = 0; j < 4; j++) v[j] = w4[i * 4 + j];
        float s = sc[gidx];
        float z = zp[gidx];
        float inv = 1.0f / s;
        uint32_t h[8];
        #pragma unroll
        for (int j = 0; j < 4; j++) {
            float q0 = fminf(15.0f, fmaxf(0.0f, rintf(__fmaf_rn(v[j].x, inv, z))));
            float q1 = fminf(15.0f, fmaxf(0.0f, rintf(__fmaf_rn(v[j].y, inv, z))));
            float q2 = fminf(15.0f, fmaxf(0.0f, rintf(__fmaf_rn(v[j].z, inv, z))));
            float q3 = fminf(15.0f, fmaxf(0.0f, rintf(__fmaf_rn(v[j].w, inv, z))));
            __half2 h0 = __floats2half2_rn((q0 - z) * s, (q1 - z) * s);
            __half2 h1 = __floats2half2_rn((q2 - z) * s, (q3 - z) * s);
            h[j * 2]     = *reinterpret_cast<uint32_t*>(&h0);
            h[j * 2 + 1] = *reinterpret_cast<uint32_t*>(&h1);
        }
        wq[i * 2]     = make_uint4(h[0], h[1], h[2], h[3]);
        wq[i * 2 + 1] = make_uint4(h[4], h[5], h[6], h[7]);
    } else {
        int i = (b - W_BLOCKS) * 256 + threadIdx.x;   // 16 elems per thread
        float4 v[4];
        #pragma unroll
        for (int j = 0; j < 4; j++) v[j] = x4[i * 4 + j];
        uint32_t h[8];
        #pragma unroll
        for (int j = 0; j < 4; j++) {
            __half2 h0 = __floats2half2_rn(v[j].x, v[j].y);
            __half2 h1 = __floats2half2_rn(v[j].z, v[j].w);
            h[j * 2]     = *reinterpret_cast<uint32_t*>(&h0);
            h[j * 2 + 1] = *reinterpret_cast<uint32_t*>(&h1);
        }
        xh[i * 2]     = make_uint4(h[0], h[1], h[2], h[3]);
        xh[i * 2 + 1] = make_uint4(h[4], h[5], h[6], h[7]);
    }
}

// ---------------- kernel 2: HMMA GEMM + bias (best-measured structure) ------
// CTA 128x256, K staged by 64 with a 4-deep TMA pipeline.
// 16 consumer warps (4Mx4N grid, 32x64 warp tiles, mma.m16n8k16, f32 accum),
// 1 producer warp (warp 16) issuing TMA from a single elected thread.
__global__ void __launch_bounds__(NTHREADS, 1) qgemm_kernel(
    const __grid_constant__ CUtensorMap tmA,
    const __grid_constant__ CUtensorMap tmB,
    const float* __restrict__ bias,
    float* __restrict__ out)
{
    extern __shared__ char smem_raw[];
    uint32_t sb_raw = smem_u32(smem_raw);
    uint32_t sb = (sb_raw + 1023u) & ~1023u;   // 1024-align for SW128 atoms

    const int tid = threadIdx.x;
    const int wid = tid >> 5;
    const int lane = tid & 31;
    const int n0 = blockIdx.x * TN;     // x over N (16) so a wave shares A tiles
    const int m0 = blockIdx.y * TM;     // y over M (64)

    const uint32_t mb_full0  = sb;        // 4 x 8B
    const uint32_t mb_empty0 = sb + 64;   // 4 x 8B
    const uint32_t stage0 = sb + 1024;

    if (tid == 0) {
        #pragma unroll
        for (int s = 0; s < STAGES; s++) {
            MBARRIER_INIT(mb_full0 + 8 * s, 1);       // expect_tx arrival
            MBARRIER_INIT(mb_empty0 + 8 * s, NCONS);  // consumer warps
        }
    }
    __syncthreads();

    if (wid == NCONS) {
        // -------- producer --------
        if (elect_one()) {
            for (int kt = 0; kt < KITERS; kt++) {
                int s = kt & (STAGES - 1);
                uint32_t parity = 1u ^ ((kt >> 2) & 1u);
                mbar_wait(mb_empty0 + 8 * s, parity);
                uint32_t aDst = stage0 + s * STAGE_BYTES;
                MBARRIER_EXPECT_TX(mb_full0 + 8 * s, (uint32_t)STAGE_BYTES);
                tma_load_2d(aDst, &tmA, kt * TK, m0, mb_full0 + 8 * s);
                tma_load_2d(aDst + A_STAGE_BYTES, &tmB, kt * TK, n0, mb_full0 + 8 * s);
            }
        }
        return;
    }

    // -------- consumers: 4 warps over M (32 rows each), 4 over N (64 cols) ----
    const int wm = wid & 3;
    const int wn = wid >> 2;
    const int laneRow = lane & 15;
    const int laneKh = lane >> 4;
    const uint32_t swmask = (uint32_t)((lane & 7) << 4);
    const int g = lane >> 2;       // quad row
    const int t4 = lane & 3;       // quad col

    float acc[2][8][4];
    #pragma unroll
    for (int i = 0; i < 2; i++)
        #pragma unroll
        for (int j = 0; j < 8; j++)
            #pragma unroll
            for (int c = 0; c < 4; c++) acc[i][j][c] = 0.0f;

    // per-lane invariant parts of ldmatrix addresses
    const uint32_t aLane = (uint32_t)(laneRow * 128);
    const uint32_t kLanePart = (uint32_t)(laneKh * 16);

    #pragma unroll 1
    for (int kt = 0; kt < KITERS; kt++) {
        int s = kt & (STAGES - 1);
        uint32_t parity = (kt >> 2) & 1u;
        mbar_wait(mb_full0 + 8 * s, parity);

        uint32_t aBase = stage0 + s * STAGE_BYTES;
        uint32_t bBase = aBase + A_STAGE_BYTES;
        uint32_t aWarp = aBase + (uint32_t)(wm * 32) * 128 + aLane;
        uint32_t bWarp = bBase + (uint32_t)(wn * 64) * 128 + aLane;

        #pragma unroll
        for (int kq = 0; kq < 4; kq++) {
            uint32_t kcol = (((uint32_t)(kq * 32) + kLanePart) ^ swmask);
            uint32_t af[2][4];
            #pragma unroll
            for (int mi = 0; mi < 2; mi++)
                LDSM_X4(af[mi], aWarp + (uint32_t)(mi * 16 * 128) + kcol);
            uint32_t bf[4][4];
            #pragma unroll
            for (int nq = 0; nq < 4; nq++)
                LDSM_X4(bf[nq], bWarp + (uint32_t)(nq * 16 * 128) + kcol);
            #pragma unroll
            for (int mi = 0; mi < 2; mi++) {
                #pragma unroll
                for (int nq = 0; nq < 4; nq++) {
                    mma16816(acc[mi][2 * nq],     af[mi], bf[nq][0], bf[nq][2]);
                    mma16816(acc[mi][2 * nq + 1], af[mi], bf[nq][1], bf[nq][3]);
                }
            }
        }
        __syncwarp();
        if (lane == 0) MBARRIER_ARRIVE(mb_empty0 + 8 * s);
    }

    // -------- epilogue: bias + store --------
    const float2* b2 = reinterpret_cast<const float2*>(bias);
    #pragma unroll
    for (int mi = 0; mi < 2; mi++) {
        int mrow = m0 + wm * 32 + mi * 16 + g;
        #pragma unroll
        for (int nj = 0; nj < 8; nj++) {
            int col = n0 + wn * 64 + nj * 8 + 2 * t4;
            float2 bv = __ldg(&b2[col >> 1]);
            float2 v0, v1;
            v0.x = acc[mi][nj][0] + bv.x;
            v0.y = acc[mi][nj][1] + bv.y;
            v1.x = acc[mi][nj][2] + bv.x;
            v1.y = acc[mi][nj][3] + bv.y;
            *reinterpret_cast<float2*>(out + (size_t)mrow * N_TOTAL + col) = v0;
            *reinterpret_cast<float2*>(out + (size_t)(mrow + 8) * N_TOTAL + col) = v1;
        }
    }
}

// ---------------- host launch ----------------
typedef CUresult (*EncodeFn)(CUtensorMap*, CUtensorMapDataType, cuuint32_t, void*,
                             const cuuint64_t*, const cuuint64_t*, const cuuint32_t*,
                             const cuuint32_t*, CUtensorMapInterleave, CUtensorMapSwizzle,
                             CUtensorMapL2promotion, CUtensorMapFloatOOBfill);

extern "C" void kernel_launch(void* const* d_in, const int* in_sizes, int n_in,
                              void* d_out, int out_size) {
    const float* x    = (const float*)d_in[0];
    const float* w    = (const float*)d_in[1];
    const float* bias = (const float*)d_in[2];
    const float* sc   = (const float*)d_in[3];
    const float* zp   = (const float*)d_in[4];
    float* out = (float*)d_out;

    void* wq_ptr = nullptr;
    void* xh_ptr = nullptr;
    cudaGetSymbolAddress(&wq_ptr, g_wq);
    cudaGetSymbolAddress(&xh_ptr, g_xh);

    prep_kernel<<<W_BLOCKS + X_BLOCKS, 256>>>(
        (const float4*)w, sc, zp, (uint4*)wq_ptr,
        (const float4*)x, (uint4*)xh_ptr);

    void* fnp = nullptr;
    cudaDriverEntryPointQueryResult qres;
    cudaGetDriverEntryPointByVersion("cuTensorMapEncodeTiled", &fnp, 12000,
                                     cudaEnableDefault, &qres);
    if (!fnp) return;
    EncodeFn enc = (EncodeFn)fnp;

    CUtensorMap tmA, tmB;
    {
        cuuint64_t dims[2] = {(cuuint64_t)K_TOTAL, (cuuint64_t)M_TOTAL};
        cuuint64_t str[1]  = {(cuuint64_t)K_TOTAL * 2};
        cuuint32_t box[2]  = {(cuuint32_t)TK, (cuuint32_t)TM};
        cuuint32_t es[2]   = {1, 1};
        enc(&tmA, CU_TENSOR_MAP_DATA_TYPE_FLOAT16, 2, xh_ptr, dims, str, box, es,
            CU_TENSOR_MAP_INTERLEAVE_NONE, CU_TENSOR_MAP_SWIZZLE_128B,
            CU_TENSOR_MAP_L2_PROMOTION_L2_256B, CU_TENSOR_MAP_FLOAT_OOB_FILL_NONE);
    }
    {
        cuuint64_t dims[2] = {(cuuint64_t)K_TOTAL, (cuuint64_t)N_TOTAL};
        cuuint64_t str[1]  = {(cuuint64_t)K_TOTAL * 2};
        cuuint32_t box[2]  = {(cuuint32_t)TK, (cuuint32_t)TN};
        cuuint32_t es[2]   = {1, 1};
        enc(&tmB, CU_TENSOR_MAP_DATA_TYPE_FLOAT16, 2, wq_ptr, dims, str, box, es,
            CU_TENSOR_MAP_INTERLEAVE_NONE, CU_TENSOR_MAP_SWIZZLE_128B,
            CU_TENSOR_MAP_L2_PROMOTION_L2_256B, CU_TENSOR_MAP_FLOAT_OOB_FILL_NONE);
    }

    cudaFuncSetAttribute(qgemm_kernel, cudaFuncAttributeMaxDynamicSharedMemorySize,
                         (int)SMEM_BYTES);
    qgemm_kernel<<<dim3(N_TOTAL / TN, M_TOTAL / TM, 1), NTHREADS, SMEM_BYTES>>>(
        tmA, tmB, bias, out);
}